// round 7
// baseline (speedup 1.0000x reference)
#include <cuda_runtime.h>
#include <cuda_bf16.h>

// Reference analysis (verified rel_err=0.0 in R2/R3):
//   OD        = tanh(...)               -> fp32 in (-1, 1], saturates at exactly 1.0f
//   adjacency = where(OD > 1.0, OD, 0)  -> strict '>' vs tanh output: identically 0
//   output[b, t, 0] = adjacency[cur, nxt] -> identically 0 for all [256, 199, 1]
// Entire GAT stack / OD matrix / gumbel walks are dead code w.r.t. the output.
//
// R4 experiment: minimal SM kernel node vs CE memset node (R3: 4.86us).
// out_size = 256*199 = 50944 floats = 6368 chunks of 8 floats (exact, no tail).
// 25 CTAs x 256 threads = 6400 threads, one guard, two STG.128 per thread,
// no integer tail path. Tests whether the kernel-node replay floor beats the
// memset-node floor once CTA ramp and instruction count are minimized.

__global__ void __launch_bounds__(256, 1) zero_out_min(float4* __restrict__ out, int n8) {
    int i = blockIdx.x * 256 + threadIdx.x;
    if (i < n8) {
        const float4 z = make_float4(0.f, 0.f, 0.f, 0.f);
        out[i * 2 + 0] = z;
        out[i * 2 + 1] = z;
    }
}

extern "C" void kernel_launch(void* const* d_in, const int* in_sizes, int n_in,
                              void* d_out, int out_size) {
    (void)d_in; (void)in_sizes; (void)n_in;
    // out_size floats; write in 32-byte (2 x float4) chunks. 50944 % 8 == 0,
    // but keep a byte-exact fallback for any remainder via memset of the tail.
    int n8 = out_size >> 3;             // number of 32B chunks
    int blocks = (n8 + 255) / 256;
    if (blocks < 1) blocks = 1;
    zero_out_min<<<blocks, 256>>>((float4*)d_out, n8);
    int rem = out_size - (n8 << 3);     // 0 for this problem
    if (rem > 0) {
        cudaMemsetAsync((float*)d_out + (n8 << 3), 0, (size_t)rem * sizeof(float));
    }
}